// round 12
// baseline (speedup 1.0000x reference)
#include <cuda_runtime.h>
#include <cstdint>

// TVLoss: circular-gradient magnitude mean (== reference's FFT path).
//   gx[i,j] = f[i,j] - f[i,(j+1)%W]
//   gy[i,j] = f[i,j] - f[(i+1)%H,j]
//   out = mean( sqrt(gx^2 + gy^2) )
//
// R12: equal-work single-wave grid. 1184 blocks (8/SM, all resident,
// regs<=32 -> 100% occupancy) x 256 thr = 2368 half-block workers. The
// 96*512 = 49152 global rows are split into 2368 contiguous ranges of
// 768/37 (~20.76) rows each -> per-worker imbalance is +-1 row, no wave
// quantization, no block-level tail. Rolling self=down reuse (~1.05x read
// traffic), shfl right-neighbor, fused last-block reduction.

static constexpr int B = 32, C = 3, H = 512, W = 512;
static constexpr long long TOTAL = (long long)B * C * H * W;   // 25,165,824
static constexpr int GROWS = B * C * H;            // 49152 global rows
static constexpr int W4    = W / 4;                // 128 float4 per row
static constexpr int NTHR  = 256;                  // 2 workers/block
static constexpr int NBLK  = 1184;                 // 148 SMs * 8 blocks
static constexpr int NWORK = NBLK * 2;             // 2368 workers
// rows per worker = GROWS/NWORK = 768/37

__device__ float    g_partials[NBLK];
__device__ unsigned g_count = 0;

__device__ __forceinline__ float fsqrt_approx(float x) {
    float r;
    asm("sqrt.approx.f32 %0, %1;" : "=f"(r) : "f"(x));
    return r;
}

__global__ __launch_bounds__(NTHR, 8)
void tv_fused(const float4* __restrict__ in4, float* __restrict__ out) {
    const float* __restrict__ inf = (const float*)in4;

    const int tid  = threadIdx.x;
    const int c4   = tid & (W4 - 1);               // column (float4 units)
    const int wk   = blockIdx.x * 2 + (tid >> 7);  // worker id (0..2367)
    const int lane = tid & 31;
    const int rc4  = (c4 + 1) & (W4 - 1);          // right-neighbor column

    // contiguous global-row range for this worker: [r0, r1)
    const int r0 = (wk * 768) / 37;                // wk*GROWS/NWORK
    const int r1 = ((wk + 1) * 768) / 37;

    float acc = 0.0f;

    float4 s = in4[(r0 << 7) + c4];

    #pragma unroll 4
    for (int g = r0; g < r1; ++g) {
        const bool wrap = ((g & (H - 1)) == (H - 1));       // last row of plane
        const int  drow = wrap ? g - (H - 1) : g + 1;       // circular down row
        const float4 d  = in4[(drow << 7) + c4];

        float rn = __shfl_down_sync(0xFFFFFFFFu, s.x, 1);
        if (lane == 31)
            rn = __ldg(&inf[(g << 9) + (rc4 << 2)]);

        const float dx0 = s.x - s.y, dx1 = s.y - s.z;
        const float dx2 = s.z - s.w, dx3 = s.w - rn;
        const float dy0 = s.x - d.x, dy1 = s.y - d.y;
        const float dy2 = s.z - d.z, dy3 = s.w - d.w;

        acc += fsqrt_approx(fmaf(dx0, dx0, dy0 * dy0));
        acc += fsqrt_approx(fmaf(dx1, dx1, dy1 * dy1));
        acc += fsqrt_approx(fmaf(dx2, dx2, dy2 * dy2));
        acc += fsqrt_approx(fmaf(dx3, dx3, dy3 * dy3));

        // next row's self: normally == d; at a plane boundary reload row g+1
        if (wrap && g + 1 < r1) s = in4[((g + 1) << 7) + c4];
        else                    s = d;
    }

    // ── block reduce (8 warps) ──
    #pragma unroll
    for (int o = 16; o; o >>= 1) acc += __shfl_xor_sync(0xFFFFFFFFu, acc, o);

    __shared__ float smem[NTHR / 32];
    if (lane == 0) smem[tid >> 5] = acc;
    __syncthreads();

    if (tid < 32) {
        float v = (tid < NTHR / 32) ? smem[tid] : 0.0f;
        #pragma unroll
        for (int o = 4; o; o >>= 1) v += __shfl_xor_sync(0xFFFFFFFFu, v, o);
        if (tid == 0) g_partials[blockIdx.x] = v;
    }

    // ── last-block final reduction ──
    __shared__ bool amLast;
    if (tid == 0) {
        __threadfence();
        unsigned prev = atomicAdd(&g_count, 1u);
        amLast = (prev == (unsigned)(NBLK - 1));
    }
    __syncthreads();

    if (amLast) {
        float v = 0.0f;
        for (int i = tid; i < NBLK; i += NTHR) v += g_partials[i];
        #pragma unroll
        for (int o = 16; o; o >>= 1) v += __shfl_xor_sync(0xFFFFFFFFu, v, o);

        __shared__ float sm2[NTHR / 32];
        if (lane == 0) sm2[tid >> 5] = v;
        __syncthreads();
        if (tid < 32) {
            float w = (tid < NTHR / 32) ? sm2[tid] : 0.0f;
            #pragma unroll
            for (int o = 4; o; o >>= 1) w += __shfl_xor_sync(0xFFFFFFFFu, w, o);
            if (tid == 0) {
                out[0] = w / (float)TOTAL;
                g_count = 0;                       // reset for next graph replay
            }
        }
    }
}

extern "C" void kernel_launch(void* const* d_in, const int* in_sizes, int n_in,
                              void* d_out, int out_size) {
    tv_fused<<<NBLK, NTHR>>>((const float4*)d_in[0], (float*)d_out);
}